// round 2
// baseline (speedup 1.0000x reference)
#include <cuda_runtime.h>
#include <math.h>

#define NN_CAP 100000
#define EE_CAP 1600000
#define D      64
#define ED     16

// Scratch (no allocations allowed): xp projection table + per-node edge counts.
__device__ float g_xp[NN_CAP * D];
__device__ float g_cnt[NN_CAP];

// ---------------------------------------------------------------------------
// Kernel 0: zero output + counts
// ---------------------------------------------------------------------------
__global__ void zero_kernel(float* __restrict__ out, int out_n, int n_nodes) {
    int i = blockIdx.x * blockDim.x + threadIdx.x;
    if (i < out_n) out[i] = 0.0f;
    if (i < n_nodes) g_cnt[i] = 0.0f;
}

// ---------------------------------------------------------------------------
// Kernel 1: xp = x @ W_node^T + b_node   (x:[N,64], W:[64,64] row-major [o][i])
// Tile: 64 nodes x 64 outputs per 256-thread block, 4x4 micro-tile per thread.
// ---------------------------------------------------------------------------
__global__ void gemm_xp_kernel(const float* __restrict__ x,
                               const float* __restrict__ W,
                               const float* __restrict__ b,
                               int n_nodes) {
    __shared__ float Ws[64][68];  // Ws[i][o]  (transposed)
    __shared__ float Xs[64][68];  // Xs[i][n]

    const int tid = threadIdx.x;
    const int node0 = blockIdx.x * 64;

    // Load W transposed into smem: 4096 floats; 256 threads x 4 float4
    #pragma unroll
    for (int t = tid; t < 64 * 16; t += 256) {
        int o = t >> 4;
        int i4 = (t & 15) << 2;
        float4 w = *reinterpret_cast<const float4*>(&W[o * 64 + i4]);
        Ws[i4 + 0][o] = w.x;
        Ws[i4 + 1][o] = w.y;
        Ws[i4 + 2][o] = w.z;
        Ws[i4 + 3][o] = w.w;
    }
    // Load x tile transposed into smem
    #pragma unroll
    for (int t = tid; t < 64 * 16; t += 256) {
        int n = t >> 4;
        int i4 = (t & 15) << 2;
        int gn = node0 + n;
        float4 v = make_float4(0.f, 0.f, 0.f, 0.f);
        if (gn < n_nodes)
            v = *reinterpret_cast<const float4*>(&x[gn * 64 + i4]);
        Xs[i4 + 0][n] = v.x;
        Xs[i4 + 1][n] = v.y;
        Xs[i4 + 2][n] = v.z;
        Xs[i4 + 3][n] = v.w;
    }
    __syncthreads();

    const int tx = tid & 15;       // node group
    const int ty = tid >> 4;       // output group
    const int o0 = ty * 4;
    const int n0 = tx * 4;

    float acc[4][4];
    #pragma unroll
    for (int a = 0; a < 4; a++)
        #pragma unroll
        for (int c = 0; c < 4; c++) acc[a][c] = 0.0f;

    #pragma unroll
    for (int i = 0; i < 64; i++) {
        float4 wv = *reinterpret_cast<float4*>(&Ws[i][o0]);
        float4 xv = *reinterpret_cast<float4*>(&Xs[i][n0]);
        float wr[4] = {wv.x, wv.y, wv.z, wv.w};
        float xr[4] = {xv.x, xv.y, xv.z, xv.w};
        #pragma unroll
        for (int a = 0; a < 4; a++)
            #pragma unroll
            for (int c = 0; c < 4; c++)
                acc[a][c] = fmaf(xr[a], wr[c], acc[a][c]);
    }

    float4 bv = *reinterpret_cast<const float4*>(&b[o0]);
    #pragma unroll
    for (int a = 0; a < 4; a++) {
        int gn = node0 + n0 + a;
        if (gn < n_nodes) {
            float4 r;
            r.x = acc[a][0] + bv.x;
            r.y = acc[a][1] + bv.y;
            r.z = acc[a][2] + bv.z;
            r.w = acc[a][3] + bv.w;
            *reinterpret_cast<float4*>(&g_xp[gn * 64 + o0]) = r;
        }
    }
}

// ---------------------------------------------------------------------------
// Kernel 2: fused gate + gather + scatter.
// 16 lanes per edge: lane l computes ef[e][l]*W_edge[l], 16-lane shfl reduce
// -> gate; then lane l handles output cols [4l, 4l+4): v4 gather from xp[col],
// scale by gate, red.add.v4.f32 into out[row]. Lane 0 bumps the count.
// edge_index is int32 (JAX default x64-disabled downcasts the int64 request).
// ---------------------------------------------------------------------------
__global__ void scatter_kernel(const int* __restrict__ ei,
                               const float* __restrict__ ef,
                               const float* __restrict__ We,
                               const float* __restrict__ be,
                               float* __restrict__ out,
                               int n_edges, int n_nodes) {
    const int gtid = blockIdx.x * blockDim.x + threadIdx.x;
    int e = gtid >> 4;
    const int l = gtid & 15;
    bool valid = (e < n_edges);
    if (!valid) e = n_edges - 1;  // clamp; keep whole warp alive for shfl

    // Per-lane partial of the edge-feature dot product
    float p = __ldg(&ef[(long long)e * ED + l]) * __ldg(&We[l]);
    p += __shfl_down_sync(0xffffffffu, p, 8);
    p += __shfl_down_sync(0xffffffffu, p, 4);
    p += __shfl_down_sync(0xffffffffu, p, 2);
    p += __shfl_down_sync(0xffffffffu, p, 1);
    const int lane = threadIdx.x & 31;
    float dot = __shfl_sync(0xffffffffu, p, lane & 16);  // group base lane
    float gate = 1.0f / (1.0f + expf(-(dot + __ldg(be))));

    int row = __ldg(&ei[e]);
    int col = __ldg(&ei[n_edges + e]);

    // Defensive: any OOB index -> skip (turns dtype surprises into rel_err,
    // not a crash).
    if ((unsigned)row >= (unsigned)n_nodes || (unsigned)col >= (unsigned)n_nodes)
        valid = false;
    if (!valid) { row = 0; col = 0; }

    float4 v = *reinterpret_cast<const float4*>(&g_xp[(long long)col * D + l * 4]);
    v.x *= gate; v.y *= gate; v.z *= gate; v.w *= gate;

    if (valid) {
        float* dst = &out[(long long)row * D + l * 4];
        asm volatile("red.global.add.v4.f32 [%0], {%1, %2, %3, %4};"
                     :: "l"(dst), "f"(v.x), "f"(v.y), "f"(v.z), "f"(v.w)
                     : "memory");
        if (l == 0) atomicAdd(&g_cnt[row], 1.0f);
    }
}

// ---------------------------------------------------------------------------
// Kernel 3: mean divide. One thread per float4 of output.
// ---------------------------------------------------------------------------
__global__ void divide_kernel(float* __restrict__ out, int n_nodes) {
    int j = blockIdx.x * blockDim.x + threadIdx.x;  // float4 index
    if (j >= n_nodes * (D / 4)) return;
    int n = j >> 4;  // 16 float4 per node
    float c = g_cnt[n];
    float s = 1.0f / fmaxf(c, 1.0f);
    float4* p = reinterpret_cast<float4*>(out) + j;
    float4 v = *p;
    v.x *= s; v.y *= s; v.z *= s; v.w *= s;
    *p = v;
}

// ---------------------------------------------------------------------------
extern "C" void kernel_launch(void* const* d_in, const int* in_sizes, int n_in,
                              void* d_out, int out_size) {
    const float* x  = (const float*)d_in[0];       // [N,64]
    const int*   ei = (const int*)d_in[1];         // [2,E] int32 (see note)
    const float* ef = (const float*)d_in[2];       // [E,16]
    const float* We = (const float*)d_in[3];       // [16]
    const float* be = (const float*)d_in[4];       // [1]
    const float* Wn = (const float*)d_in[5];       // [64,64]
    const float* bn = (const float*)d_in[6];       // [64]
    float* out = (float*)d_out;                    // [N,64] f32

    int n_nodes = in_sizes[0] / D;
    int n_edges = in_sizes[2] / ED;
    if (n_nodes > NN_CAP) n_nodes = NN_CAP;
    if (n_edges > EE_CAP) n_edges = EE_CAP;

    // 0) zero output + counts
    {
        int grid = (out_size + 255) / 256;
        zero_kernel<<<grid, 256>>>(out, out_size, n_nodes);
    }
    // 1) node projection into g_xp
    {
        int grid = (n_nodes + 63) / 64;
        gemm_xp_kernel<<<grid, 256>>>(x, Wn, bn, n_nodes);
    }
    // 2) fused gate + gather + atomic scatter
    {
        long long threads = (long long)n_edges * 16;
        int grid = (int)((threads + 255) / 256);
        scatter_kernel<<<grid, 256>>>(ei, ef, We, be, out, n_edges, n_nodes);
    }
    // 3) mean
    {
        int total = n_nodes * (D / 4);
        int grid = (total + 255) / 256;
        divide_kernel<<<grid, 256>>>(out, n_nodes);
    }
}

// round 3
// speedup vs baseline: 1.5297x; 1.5297x over previous
#include <cuda_runtime.h>
#include <math.h>

#define NN_CAP 100000
#define EE_CAP 1600000
#define D      64
#define ED     16
#define CHUNK  512
#define NBLK_CAP ((NN_CAP + CHUNK - 1) / CHUNK)   // 196

// Scratch (no allocations allowed).
__device__ float g_xp[NN_CAP * D];        // projected nodes
__device__ int   g_hist[NN_CAP];          // per-node in-degree
__device__ int   g_pos[NN_CAP];           // per-node fill cursor
__device__ int   g_off[NN_CAP + 1];       // CSR offsets
__device__ int   g_partial[256];          // scan block partials
__device__ int2  g_sedge[EE_CAP];         // CSR payload: (col, gate bits)

// ---------------------------------------------------------------------------
// K0: zero histogram + cursors
// ---------------------------------------------------------------------------
__global__ void init_kernel(int n_nodes) {
    int i = blockIdx.x * blockDim.x + threadIdx.x;
    if (i < n_nodes) { g_hist[i] = 0; g_pos[i] = 0; }
}

// ---------------------------------------------------------------------------
// K1: xp = x @ W_node^T + b_node   (x:[N,64], W:[64,64] row-major [o][i])
// 64 nodes x 64 outputs per 256-thread block, 4x4 micro-tile per thread.
// ---------------------------------------------------------------------------
__global__ void gemm_xp_kernel(const float* __restrict__ x,
                               const float* __restrict__ W,
                               const float* __restrict__ b,
                               int n_nodes) {
    __shared__ float Ws[64][68];  // Ws[i][o]  (transposed)
    __shared__ float Xs[64][68];  // Xs[i][n]

    const int tid = threadIdx.x;
    const int node0 = blockIdx.x * 64;

    #pragma unroll
    for (int t = tid; t < 64 * 16; t += 256) {
        int o = t >> 4;
        int i4 = (t & 15) << 2;
        float4 w = *reinterpret_cast<const float4*>(&W[o * 64 + i4]);
        Ws[i4 + 0][o] = w.x; Ws[i4 + 1][o] = w.y;
        Ws[i4 + 2][o] = w.z; Ws[i4 + 3][o] = w.w;
    }
    #pragma unroll
    for (int t = tid; t < 64 * 16; t += 256) {
        int n = t >> 4;
        int i4 = (t & 15) << 2;
        int gn = node0 + n;
        float4 v = make_float4(0.f, 0.f, 0.f, 0.f);
        if (gn < n_nodes)
            v = *reinterpret_cast<const float4*>(&x[gn * 64 + i4]);
        Xs[i4 + 0][n] = v.x; Xs[i4 + 1][n] = v.y;
        Xs[i4 + 2][n] = v.z; Xs[i4 + 3][n] = v.w;
    }
    __syncthreads();

    const int tx = tid & 15;
    const int ty = tid >> 4;
    const int o0 = ty * 4;
    const int n0 = tx * 4;

    float acc[4][4];
    #pragma unroll
    for (int a = 0; a < 4; a++)
        #pragma unroll
        for (int c = 0; c < 4; c++) acc[a][c] = 0.0f;

    #pragma unroll
    for (int i = 0; i < 64; i++) {
        float4 wv = *reinterpret_cast<float4*>(&Ws[i][o0]);
        float4 xv = *reinterpret_cast<float4*>(&Xs[i][n0]);
        float wr[4] = {wv.x, wv.y, wv.z, wv.w};
        float xr[4] = {xv.x, xv.y, xv.z, xv.w};
        #pragma unroll
        for (int a = 0; a < 4; a++)
            #pragma unroll
            for (int c = 0; c < 4; c++)
                acc[a][c] = fmaf(xr[a], wr[c], acc[a][c]);
    }

    float4 bv = *reinterpret_cast<const float4*>(&b[o0]);
    #pragma unroll
    for (int a = 0; a < 4; a++) {
        int gn = node0 + n0 + a;
        if (gn < n_nodes) {
            float4 r;
            r.x = acc[a][0] + bv.x; r.y = acc[a][1] + bv.y;
            r.z = acc[a][2] + bv.z; r.w = acc[a][3] + bv.w;
            *reinterpret_cast<float4*>(&g_xp[gn * 64 + o0]) = r;
        }
    }
}

// ---------------------------------------------------------------------------
// K2: histogram of destination rows (int atomics, spread addresses)
// ---------------------------------------------------------------------------
__global__ void hist_kernel(const int* __restrict__ ei, int n_edges, int n_nodes) {
    int e = blockIdx.x * blockDim.x + threadIdx.x;
    if (e >= n_edges) return;
    int row = __ldg(&ei[e]);
    int col = __ldg(&ei[n_edges + e]);
    if ((unsigned)row >= (unsigned)n_nodes || (unsigned)col >= (unsigned)n_nodes)
        return;
    atomicAdd(&g_hist[row], 1);
}

// ---------------------------------------------------------------------------
// K3a: per-chunk sums of histogram
// ---------------------------------------------------------------------------
__global__ void scan_partial_kernel(int n_nodes) {
    __shared__ int s[CHUNK];
    int t = threadIdx.x;
    int i = blockIdx.x * CHUNK + t;
    s[t] = (i < n_nodes) ? g_hist[i] : 0;
    __syncthreads();
    #pragma unroll
    for (int st = CHUNK / 2; st > 0; st >>= 1) {
        if (t < st) s[t] += s[t + st];
        __syncthreads();
    }
    if (t == 0) g_partial[blockIdx.x] = s[0];
}

// ---------------------------------------------------------------------------
// K3b: exclusive scan of chunk partials (single block)
// ---------------------------------------------------------------------------
__global__ void scan_root_kernel(int nblk) {
    __shared__ int s[256];
    int t = threadIdx.x;
    int v = (t < nblk) ? g_partial[t] : 0;
    s[t] = v;
    __syncthreads();
    #pragma unroll
    for (int d = 1; d < 256; d <<= 1) {
        int x = (t >= d) ? s[t - d] : 0;
        __syncthreads();
        s[t] += x;
        __syncthreads();
    }
    if (t < nblk) g_partial[t] = s[t] - v;  // exclusive
}

// ---------------------------------------------------------------------------
// K3c: final exclusive scan -> g_off[0..n], including total at g_off[n]
// ---------------------------------------------------------------------------
__global__ void scan_final_kernel(int n_nodes) {
    __shared__ int s[CHUNK];
    int t = threadIdx.x;
    int i = blockIdx.x * CHUNK + t;
    int v = (i < n_nodes) ? g_hist[i] : 0;
    s[t] = v;
    __syncthreads();
    #pragma unroll
    for (int d = 1; d < CHUNK; d <<= 1) {
        int x = (t >= d) ? s[t - d] : 0;
        __syncthreads();
        s[t] += x;
        __syncthreads();
    }
    int excl = s[t] - v + g_partial[blockIdx.x];
    if (i < n_nodes) {
        g_off[i] = excl;
        if (i == n_nodes - 1) g_off[n_nodes] = excl + v;
    }
}

// ---------------------------------------------------------------------------
// K4: permute — compute gate per edge, write (col, gate) into CSR slot.
// ---------------------------------------------------------------------------
__global__ void permute_kernel(const int* __restrict__ ei,
                               const float* __restrict__ ef,
                               const float* __restrict__ We,
                               const float* __restrict__ be,
                               int n_edges, int n_nodes) {
    int e = blockIdx.x * blockDim.x + threadIdx.x;
    if (e >= n_edges) return;
    int row = __ldg(&ei[e]);
    int col = __ldg(&ei[n_edges + e]);
    if ((unsigned)row >= (unsigned)n_nodes || (unsigned)col >= (unsigned)n_nodes)
        return;

    const float4* efp = reinterpret_cast<const float4*>(&ef[(long long)e * ED]);
    const float4* wep = reinterpret_cast<const float4*>(We);
    float dot = 0.0f;
    #pragma unroll
    for (int k = 0; k < 4; k++) {
        float4 a = __ldg(&efp[k]);
        float4 w = __ldg(&wep[k]);
        dot = fmaf(a.x, w.x, dot);
        dot = fmaf(a.y, w.y, dot);
        dot = fmaf(a.z, w.z, dot);
        dot = fmaf(a.w, w.w, dot);
    }
    float gate = 1.0f / (1.0f + expf(-(dot + __ldg(be))));

    int slot = atomicAdd(&g_pos[row], 1);
    int idx = g_off[row] + slot;
    g_sedge[idx] = make_int2(col, __float_as_int(gate));
}

// ---------------------------------------------------------------------------
// K5: accumulate + mean. 16 lanes per node, float4 accumulator per lane.
// 2-edge unroll for gather MLP. Writes every output element (no zero pass).
// ---------------------------------------------------------------------------
__global__ void accum_kernel(float* __restrict__ out, int n_nodes) {
    const int tid = threadIdx.x;
    const int node = blockIdx.x * 16 + (tid >> 4);
    const int l = tid & 15;
    if (node >= n_nodes) return;

    const int beg = __ldg(&g_off[node]);
    const int end = __ldg(&g_off[node + 1]);

    float4 acc = make_float4(0.f, 0.f, 0.f, 0.f);
    int j = beg;
    for (; j + 1 < end; j += 2) {
        int2 e0 = *reinterpret_cast<const int2*>(&g_sedge[j]);
        int2 e1 = *reinterpret_cast<const int2*>(&g_sedge[j + 1]);
        float4 v0 = *reinterpret_cast<const float4*>(&g_xp[(long long)e0.x * D + l * 4]);
        float4 v1 = *reinterpret_cast<const float4*>(&g_xp[(long long)e1.x * D + l * 4]);
        float g0 = __int_as_float(e0.y);
        float g1 = __int_as_float(e1.y);
        acc.x = fmaf(g0, v0.x, acc.x); acc.y = fmaf(g0, v0.y, acc.y);
        acc.z = fmaf(g0, v0.z, acc.z); acc.w = fmaf(g0, v0.w, acc.w);
        acc.x = fmaf(g1, v1.x, acc.x); acc.y = fmaf(g1, v1.y, acc.y);
        acc.z = fmaf(g1, v1.z, acc.z); acc.w = fmaf(g1, v1.w, acc.w);
    }
    if (j < end) {
        int2 e0 = *reinterpret_cast<const int2*>(&g_sedge[j]);
        float4 v0 = *reinterpret_cast<const float4*>(&g_xp[(long long)e0.x * D + l * 4]);
        float g0 = __int_as_float(e0.y);
        acc.x = fmaf(g0, v0.x, acc.x); acc.y = fmaf(g0, v0.y, acc.y);
        acc.z = fmaf(g0, v0.z, acc.z); acc.w = fmaf(g0, v0.w, acc.w);
    }

    int cnt = end - beg;
    float s = 1.0f / (float)max(cnt, 1);
    acc.x *= s; acc.y *= s; acc.z *= s; acc.w *= s;
    *reinterpret_cast<float4*>(&out[(long long)node * D + l * 4]) = acc;
}

// ---------------------------------------------------------------------------
extern "C" void kernel_launch(void* const* d_in, const int* in_sizes, int n_in,
                              void* d_out, int out_size) {
    const float* x  = (const float*)d_in[0];       // [N,64]
    const int*   ei = (const int*)d_in[1];         // [2,E] int32
    const float* ef = (const float*)d_in[2];       // [E,16]
    const float* We = (const float*)d_in[3];       // [16]
    const float* be = (const float*)d_in[4];       // [1]
    const float* Wn = (const float*)d_in[5];       // [64,64]
    const float* bn = (const float*)d_in[6];       // [64]
    float* out = (float*)d_out;                    // [N,64] f32

    int n_nodes = in_sizes[0] / D;
    int n_edges = in_sizes[2] / ED;
    if (n_nodes > NN_CAP) n_nodes = NN_CAP;
    if (n_edges > EE_CAP) n_edges = EE_CAP;

    int nblk = (n_nodes + CHUNK - 1) / CHUNK;      // <= 196 <= 256

    // K0: zero histogram + cursors
    init_kernel<<<(n_nodes + 255) / 256, 256>>>(n_nodes);
    // K1: node projection
    gemm_xp_kernel<<<(n_nodes + 63) / 64, 256>>>(x, Wn, bn, n_nodes);
    // K2: in-degree histogram
    hist_kernel<<<(n_edges + 255) / 256, 256>>>(ei, n_edges, n_nodes);
    // K3: exclusive scan -> CSR offsets
    scan_partial_kernel<<<nblk, CHUNK>>>(n_nodes);
    scan_root_kernel<<<1, 256>>>(nblk);
    scan_final_kernel<<<nblk, CHUNK>>>(n_nodes);
    // K4: gate + CSR permute
    permute_kernel<<<(n_edges + 255) / 256, 256>>>(ei, ef, We, be, n_edges, n_nodes);
    // K5: gather-accumulate + mean
    accum_kernel<<<(n_nodes + 15) / 16, 256>>>(out, n_nodes);
}

// round 6
// speedup vs baseline: 1.5757x; 1.0301x over previous
#include <cuda_runtime.h>
#include <math.h>

#define NN_CAP 100000
#define EE_CAP 1600000
#define D      64
#define ED     16
#define CHUNK  512

// Scratch (no allocations allowed) — same footprint class as the passing R3.
__device__ float g_xp[NN_CAP * D];        // projected nodes (25.6 MB)
__device__ int   g_hist[NN_CAP];          // per-node in-degree
__device__ int   g_pos[NN_CAP];           // per-node fill cursor
__device__ int   g_off[NN_CAP + 1];       // CSR offsets
__device__ int   g_partial[256];          // chunk partial sums
__device__ int2  g_sedge[EE_CAP];         // CSR payload: (col, gate bits) (12.8 MB)

// ---------------------------------------------------------------------------
// K0: zero histogram + cursors
// ---------------------------------------------------------------------------
__global__ void init_kernel(int n_nodes) {
    int i = blockIdx.x * blockDim.x + threadIdx.x;
    if (i < n_nodes) { g_hist[i] = 0; g_pos[i] = 0; }
}

// ---------------------------------------------------------------------------
// K1: xp = x @ W_node^T + b_node   (x:[N,64], W:[64,64] row-major [o][i])
// ---------------------------------------------------------------------------
__global__ void __launch_bounds__(256) gemm_xp_kernel(
        const float* __restrict__ x,
        const float* __restrict__ W,
        const float* __restrict__ b,
        int n_nodes) {
    __shared__ float Ws[64][68];  // Ws[i][o]
    __shared__ float Xs[64][68];  // Xs[i][n]

    const int tid = threadIdx.x;
    const int node0 = blockIdx.x * 64;

    #pragma unroll
    for (int t = tid; t < 64 * 16; t += 256) {
        int o = t >> 4;
        int i4 = (t & 15) << 2;
        float4 w = *reinterpret_cast<const float4*>(&W[o * 64 + i4]);
        Ws[i4 + 0][o] = w.x; Ws[i4 + 1][o] = w.y;
        Ws[i4 + 2][o] = w.z; Ws[i4 + 3][o] = w.w;
    }
    #pragma unroll
    for (int t = tid; t < 64 * 16; t += 256) {
        int n = t >> 4;
        int i4 = (t & 15) << 2;
        int gn = node0 + n;
        float4 v = make_float4(0.f, 0.f, 0.f, 0.f);
        if (gn < n_nodes)
            v = *reinterpret_cast<const float4*>(&x[gn * 64 + i4]);
        Xs[i4 + 0][n] = v.x; Xs[i4 + 1][n] = v.y;
        Xs[i4 + 2][n] = v.z; Xs[i4 + 3][n] = v.w;
    }
    __syncthreads();

    const int tx = tid & 15;
    const int ty = tid >> 4;
    const int o0 = ty * 4;
    const int n0 = tx * 4;

    float acc[4][4];
    #pragma unroll
    for (int a = 0; a < 4; a++)
        #pragma unroll
        for (int c = 0; c < 4; c++) acc[a][c] = 0.0f;

    #pragma unroll
    for (int i = 0; i < 64; i++) {
        float4 wv = *reinterpret_cast<float4*>(&Ws[i][o0]);
        float4 xv = *reinterpret_cast<float4*>(&Xs[i][n0]);
        float wr[4] = {wv.x, wv.y, wv.z, wv.w};
        float xr[4] = {xv.x, xv.y, xv.z, xv.w};
        #pragma unroll
        for (int a = 0; a < 4; a++)
            #pragma unroll
            for (int c = 0; c < 4; c++)
                acc[a][c] = fmaf(xr[a], wr[c], acc[a][c]);
    }

    float4 bv = *reinterpret_cast<const float4*>(&b[o0]);
    #pragma unroll
    for (int a = 0; a < 4; a++) {
        int gn = node0 + n0 + a;
        if (gn < n_nodes) {
            float4 r;
            r.x = acc[a][0] + bv.x; r.y = acc[a][1] + bv.y;
            r.z = acc[a][2] + bv.z; r.w = acc[a][3] + bv.w;
            *reinterpret_cast<float4*>(&g_xp[gn * 64 + o0]) = r;
        }
    }
}

// ---------------------------------------------------------------------------
// K2: histogram of destination rows
// ---------------------------------------------------------------------------
__global__ void hist_kernel(const int* __restrict__ ei, int n_edges, int n_nodes) {
    int e = blockIdx.x * blockDim.x + threadIdx.x;
    if (e >= n_edges) return;
    int row = __ldg(&ei[e]);
    int col = __ldg(&ei[n_edges + e]);
    if ((unsigned)row >= (unsigned)n_nodes || (unsigned)col >= (unsigned)n_nodes)
        return;
    atomicAdd(&g_hist[row], 1);
}

// ---------------------------------------------------------------------------
// K3a: per-chunk sums (warp-shfl reduce; minimal syncs)
// ---------------------------------------------------------------------------
__global__ void scan_partial_kernel(int n_nodes) {
    int i = blockIdx.x * CHUNK + threadIdx.x;
    int v = (i < n_nodes) ? g_hist[i] : 0;
    #pragma unroll
    for (int o = 16; o; o >>= 1) v += __shfl_down_sync(0xffffffffu, v, o);
    __shared__ int s[16];
    if ((threadIdx.x & 31) == 0) s[threadIdx.x >> 5] = v;
    __syncthreads();
    if (threadIdx.x < 16) {
        int t = s[threadIdx.x];
        #pragma unroll
        for (int o = 8; o; o >>= 1) t += __shfl_down_sync(0xffffu, t, o, 16);
        if (threadIdx.x == 0) g_partial[blockIdx.x] = t;
    }
}

// ---------------------------------------------------------------------------
// K3b: final scan. Each block: warp-scan local chunk + inline prefix of the
// (<=196) chunk partials. Writes g_off[0..n] including total.
// ---------------------------------------------------------------------------
__global__ void scan_final_kernel(int n_nodes) {
    const int tid = threadIdx.x;
    const int bid = blockIdx.x;
    const int lane = tid & 31;
    const int wid = tid >> 5;
    int i = bid * CHUNK + tid;
    int v = (i < n_nodes) ? g_hist[i] : 0;

    // inclusive warp scan of v
    int x = v;
    #pragma unroll
    for (int o = 1; o < 32; o <<= 1) {
        int y = __shfl_up_sync(0xffffffffu, x, o);
        if (lane >= o) x += y;
    }

    __shared__ int wsum[16];
    __shared__ int blockpref;
    if (lane == 31) wsum[wid] = x;
    if (tid < 32) {
        int acc = 0;
        for (int k = lane; k < bid; k += 32) acc += g_partial[k];
        #pragma unroll
        for (int o = 16; o; o >>= 1) acc += __shfl_down_sync(0xffffffffu, acc, o);
        if (lane == 0) blockpref = acc;
    }
    __syncthreads();
    if (tid < 16) {
        int t = wsum[tid];
        #pragma unroll
        for (int o = 1; o < 16; o <<= 1) {
            int y = __shfl_up_sync(0xffffu, t, o, 16);
            if (tid >= o) t += y;
        }
        wsum[tid] = t;  // inclusive over warps
    }
    __syncthreads();

    int warppref = (wid == 0) ? 0 : wsum[wid - 1];
    int incl = x + warppref + blockpref;
    int excl = incl - v;
    if (i < n_nodes) {
        g_off[i] = excl;
        if (i == n_nodes - 1) g_off[n_nodes] = incl;
    }
}

// ---------------------------------------------------------------------------
// K4: permute — compute gate per edge, write (col, gate) into CSR slot.
// ---------------------------------------------------------------------------
__global__ void __launch_bounds__(256) permute_kernel(
        const int* __restrict__ ei,
        const float* __restrict__ ef,
        const float* __restrict__ We,
        const float* __restrict__ be,
        int n_edges, int n_nodes) {
    int e = blockIdx.x * blockDim.x + threadIdx.x;
    if (e >= n_edges) return;
    int row = __ldg(&ei[e]);
    int col = __ldg(&ei[n_edges + e]);
    if ((unsigned)row >= (unsigned)n_nodes || (unsigned)col >= (unsigned)n_nodes)
        return;

    const float4* efp = reinterpret_cast<const float4*>(&ef[(long long)e * ED]);
    const float4* wep = reinterpret_cast<const float4*>(We);
    float dot = 0.0f;
    #pragma unroll
    for (int k = 0; k < 4; k++) {
        float4 a = __ldg(&efp[k]);
        float4 w = __ldg(&wep[k]);
        dot = fmaf(a.x, w.x, dot);
        dot = fmaf(a.y, w.y, dot);
        dot = fmaf(a.z, w.z, dot);
        dot = fmaf(a.w, w.w, dot);
    }
    float gate = 1.0f / (1.0f + expf(-(dot + __ldg(be))));

    int slot = atomicAdd(&g_pos[row], 1);
    g_sedge[g_off[row] + slot] = make_int2(col, __float_as_int(gate));
}

// ---------------------------------------------------------------------------
// K5: accumulate + mean. 16 lanes per node, float4 accumulator per lane.
// Alignment prologue, then 4 edges/iter via two int4 loads (2 edges / 16B).
// ---------------------------------------------------------------------------
__global__ void __launch_bounds__(256) accum_kernel(
        float* __restrict__ out, int n_nodes) {
    const int tid = threadIdx.x;
    const int node = blockIdx.x * 16 + (tid >> 4);
    const int l = tid & 15;
    if (node >= n_nodes) return;

    const int beg = __ldg(&g_off[node]);
    const int end = __ldg(&g_off[node + 1]);

    float4 acc = make_float4(0.f, 0.f, 0.f, 0.f);
    int j = beg;

    // prologue: reach 16B (even-index) alignment of g_sedge
    if ((j & 1) && j < end) {
        int2 e0 = __ldg(&g_sedge[j]);
        float4 v0 = *reinterpret_cast<const float4*>(&g_xp[(size_t)e0.x * D + l * 4]);
        float g0 = __int_as_float(e0.y);
        acc.x = fmaf(g0, v0.x, acc.x); acc.y = fmaf(g0, v0.y, acc.y);
        acc.z = fmaf(g0, v0.z, acc.z); acc.w = fmaf(g0, v0.w, acc.w);
        j++;
    }
    const int4* eb = reinterpret_cast<const int4*>(g_sedge);
    for (; j + 3 < end; j += 4) {
        int4 p0 = __ldg(&eb[(j >> 1) + 0]);   // (col0, g0, col1, g1)
        int4 p1 = __ldg(&eb[(j >> 1) + 1]);   // (col2, g2, col3, g3)
        float4 v0 = *reinterpret_cast<const float4*>(&g_xp[(size_t)p0.x * D + l * 4]);
        float4 v1 = *reinterpret_cast<const float4*>(&g_xp[(size_t)p0.z * D + l * 4]);
        float4 v2 = *reinterpret_cast<const float4*>(&g_xp[(size_t)p1.x * D + l * 4]);
        float4 v3 = *reinterpret_cast<const float4*>(&g_xp[(size_t)p1.z * D + l * 4]);
        float g0 = __int_as_float(p0.y);
        float g1 = __int_as_float(p0.w);
        float g2 = __int_as_float(p1.y);
        float g3 = __int_as_float(p1.w);
        acc.x = fmaf(g0, v0.x, acc.x); acc.y = fmaf(g0, v0.y, acc.y);
        acc.z = fmaf(g0, v0.z, acc.z); acc.w = fmaf(g0, v0.w, acc.w);
        acc.x = fmaf(g1, v1.x, acc.x); acc.y = fmaf(g1, v1.y, acc.y);
        acc.z = fmaf(g1, v1.z, acc.z); acc.w = fmaf(g1, v1.w, acc.w);
        acc.x = fmaf(g2, v2.x, acc.x); acc.y = fmaf(g2, v2.y, acc.y);
        acc.z = fmaf(g2, v2.z, acc.z); acc.w = fmaf(g2, v2.w, acc.w);
        acc.x = fmaf(g3, v3.x, acc.x); acc.y = fmaf(g3, v3.y, acc.y);
        acc.z = fmaf(g3, v3.z, acc.z); acc.w = fmaf(g3, v3.w, acc.w);
    }
    for (; j < end; j++) {
        int2 e0 = __ldg(&g_sedge[j]);
        float4 v0 = *reinterpret_cast<const float4*>(&g_xp[(size_t)e0.x * D + l * 4]);
        float g0 = __int_as_float(e0.y);
        acc.x = fmaf(g0, v0.x, acc.x); acc.y = fmaf(g0, v0.y, acc.y);
        acc.z = fmaf(g0, v0.z, acc.z); acc.w = fmaf(g0, v0.w, acc.w);
    }

    int cnt = end - beg;
    float s = 1.0f / (float)(cnt > 1 ? cnt : 1);
    acc.x *= s; acc.y *= s; acc.z *= s; acc.w *= s;
    *reinterpret_cast<float4*>(&out[(size_t)node * D + l * 4]) = acc;
}

// ---------------------------------------------------------------------------
extern "C" void kernel_launch(void* const* d_in, const int* in_sizes, int n_in,
                              void* d_out, int out_size) {
    const float* x  = (const float*)d_in[0];       // [N,64]
    const int*   ei = (const int*)d_in[1];         // [2,E] int32
    const float* ef = (const float*)d_in[2];       // [E,16]
    const float* We = (const float*)d_in[3];       // [16]
    const float* be = (const float*)d_in[4];       // [1]
    const float* Wn = (const float*)d_in[5];       // [64,64]
    const float* bn = (const float*)d_in[6];       // [64]
    float* out = (float*)d_out;                    // [N,64] f32

    int n_nodes = in_sizes[0] / D;
    int n_edges = in_sizes[2] / ED;
    if (n_nodes > NN_CAP) n_nodes = NN_CAP;
    if (n_edges > EE_CAP) n_edges = EE_CAP;

    int nblk = (n_nodes + CHUNK - 1) / CHUNK;      // <= 196 <= 256

    init_kernel<<<(n_nodes + 255) / 256, 256>>>(n_nodes);
    gemm_xp_kernel<<<(n_nodes + 63) / 64, 256>>>(x, Wn, bn, n_nodes);
    hist_kernel<<<(n_edges + 255) / 256, 256>>>(ei, n_edges, n_nodes);
    scan_partial_kernel<<<nblk, CHUNK>>>(n_nodes);
    scan_final_kernel<<<nblk, CHUNK>>>(n_nodes);
    permute_kernel<<<(n_edges + 255) / 256, 256>>>(ei, ef, We, be, n_edges, n_nodes);
    accum_kernel<<<(n_nodes + 15) / 16, 256>>>(out, n_nodes);
}